// round 16
// baseline (speedup 1.0000x reference)
#include <cuda_runtime.h>
#include <cuda_bf16.h>
#include <cstdint>

// Problem constants
#define Bn   32
#define Tn   256
#define Un   128
#define Um1  127
#define Vn   4096
#define ND   383            // number of anti-diagonals (Tn+Un-1)

// ---------------- device scratch ---------------------------------------------
__device__ __align__(16) __nv_bfloat16 g_expE[(size_t)Bn * Tn * Vn]; // exp(E) bf16
__device__ __align__(16) __nv_bfloat16 g_expP[(size_t)Bn * Un * Vn]; // exp(P) bf16
__device__ __align__(16) float gd_blank[(size_t)Bn * ND * 128]; // diag-major blank_lp
__device__ __align__(16) float gd_lab  [(size_t)Bn * ND * 128]; // diag-major lab_lp

// ---------------- PTX helpers ------------------------------------------------
__device__ __forceinline__ uint32_t smem_u32(const void* p) {
    uint32_t a;
    asm("{ .reg .u64 t; cvta.to.shared.u64 t, %1; cvt.u32.u64 %0, t; }"
        : "=r"(a) : "l"(p));
    return a;
}
#define CP16(dst, src)   asm volatile("cp.async.cg.shared.global [%0], [%1], 16;" :: "r"(dst), "l"(src) : "memory")
#define CP_COMMIT()      asm volatile("cp.async.commit_group;" ::: "memory")

#define LDSM4(r0, r1, r2, r3, addr) \
    asm volatile("ldmatrix.sync.aligned.m8n8.x4.shared.b16 {%0,%1,%2,%3}, [%4];" \
        : "=r"(r0), "=r"(r1), "=r"(r2), "=r"(r3) : "r"(addr))

#define MMA16816(c, a, bq) \
    asm volatile("mma.sync.aligned.m16n8k16.row.col.f32.bf16.bf16.f32 " \
        "{%0,%1,%2,%3}, {%4,%5,%6,%7}, {%8,%9}, {%0,%1,%2,%3};" \
        : "+f"((c)[0]), "+f"((c)[1]), "+f"((c)[2]), "+f"((c)[3]) \
        : "r"((a)[0]), "r"((a)[1]), "r"((a)[2]), "r"((a)[3]), \
          "r"((bq)[0]), "r"((bq)[1]))

// ---------------- kernel 1: exp + bf16 convert -------------------------------
__global__ void expcvt_kernel(const float* __restrict__ E,
                              const float* __restrict__ P) {
    const size_t NE = (size_t)Bn * Tn * Vn;
    size_t i = ((size_t)blockIdx.x * 256 + threadIdx.x) * 8;
    const float* src;
    __nv_bfloat16* dst;
    if (i < NE) { src = E + i; dst = g_expE + i; }
    else        { src = P + (i - NE); dst = g_expP + (i - NE); }
    float4 v0 = *(const float4*)(src);
    float4 v1 = *(const float4*)(src + 4);
    __nv_bfloat162 o[4];
    o[0] = __floats2bfloat162_rn(__expf(v0.x), __expf(v0.y));
    o[1] = __floats2bfloat162_rn(__expf(v0.z), __expf(v0.w));
    o[2] = __floats2bfloat162_rn(__expf(v1.x), __expf(v1.y));
    o[3] = __floats2bfloat162_rn(__expf(v1.z), __expf(v1.w));
    uint4 pk;
    pk.x = *(uint32_t*)&o[0]; pk.y = *(uint32_t*)&o[1];
    pk.z = *(uint32_t*)&o[2]; pk.w = *(uint32_t*)&o[3];
    *(uint4*)dst = pk;
}

// ---------------- kernel 2: HMMA GEMM, 6-stage pipeline (round-9, best) ------
#define SMEM_HDR  2048
#define STAGE_B   24576
#define NSTAGE    6
#define SMEM_TOT  (SMEM_HDR + NSTAGE * STAGE_B)   // 149504

__global__ __launch_bounds__(256, 1) void gemm_kernel(const float* __restrict__ E,
                                                      const float* __restrict__ P,
                                                      const int* __restrict__ labels) {
    extern __shared__ __align__(1024) char smem[];
    uint32_t sb = smem_u32(smem);
    float* p0s = (float*)(smem);
    float* pls = (float*)(smem + 512);
    int*   lbs = (int*)(smem + 1024);

    int tid = threadIdx.x, lane = tid & 31, wid = tid >> 5;
    int wm = wid >> 2;
    int wn = wid & 3;
    int t0 = blockIdx.x * 64;
    int b  = blockIdx.y;

    if (tid < Un) {
        const float* Pr = P + (size_t)(b * Un + tid) * Vn;
        p0s[tid] = Pr[0];
        if (tid < Um1) {
            int l = labels[b * Um1 + tid];
            lbs[tid] = l;
            pls[tid] = Pr[l];
        }
    }

    auto issue = [&](int k) {
        uint32_t base = sb + SMEM_HDR + (k % NSTAGE) * STAGE_B;
        int r = tid >> 3, c = tid & 7;
        uint32_t sw = (uint32_t)((c ^ (r & 7)) << 4);
        const __nv_bfloat16* asrc = g_expE + (size_t)(b * Tn + t0 + r) * Vn + k * 64 + c * 8;
        CP16(base + r * 128 + sw,        asrc);
        CP16(base + (r + 32) * 128 + sw, asrc + (size_t)32 * Vn);
        const __nv_bfloat16* bsrc = g_expP + (size_t)(b * Un + r) * Vn + k * 64 + c * 8;
        uint32_t bb = base + 8192;
#pragma unroll
        for (int q = 0; q < 4; q++)
            CP16(bb + (r + q * 32) * 128 + sw, bsrc + (size_t)(q * 32) * Vn);
        CP_COMMIT();
    };

    issue(0); issue(1); issue(2); issue(3); issue(4);

    float cr[2][4][4] = {};

    for (int k = 0; k < 64; k++) {
        if      (k <= 59) asm volatile("cp.async.wait_group 4;" ::: "memory");
        else if (k == 60) asm volatile("cp.async.wait_group 3;" ::: "memory");
        else if (k == 61) asm volatile("cp.async.wait_group 2;" ::: "memory");
        else if (k == 62) asm volatile("cp.async.wait_group 1;" ::: "memory");
        else              asm volatile("cp.async.wait_group 0;" ::: "memory");
        __syncthreads();
        if (k + 5 < 64) issue(k + 5);

        uint32_t sA = sb + SMEM_HDR + (k % NSTAGE) * STAGE_B;
        uint32_t sB = sA + 8192;
#pragma unroll
        for (int kf = 0; kf < 4; kf++) {
            uint32_t afr[2][4], bfr[4][2];
#pragma unroll
            for (int mi = 0; mi < 2; mi++) {
                int row = wm * 32 + mi * 16 + (lane & 15);
                int kc  = kf * 2 + (lane >> 4);
                uint32_t ad = sA + row * 128 + (((uint32_t)(kc ^ (row & 7))) << 4);
                LDSM4(afr[mi][0], afr[mi][1], afr[mi][2], afr[mi][3], ad);
            }
#pragma unroll
            for (int p = 0; p < 2; p++) {
                int g = lane >> 3;
                int nrow = wn * 32 + p * 16 + ((g >> 1) << 3) + (lane & 7);
                int kc   = kf * 2 + (g & 1);
                uint32_t bd = sB + nrow * 128 + (((uint32_t)(kc ^ (nrow & 7))) << 4);
                uint32_t r0, r1, r2, r3;
                LDSM4(r0, r1, r2, r3, bd);
                bfr[p * 2 + 0][0] = r0; bfr[p * 2 + 0][1] = r1;
                bfr[p * 2 + 1][0] = r2; bfr[p * 2 + 1][1] = r3;
            }
#pragma unroll
            for (int mi = 0; mi < 2; mi++)
#pragma unroll
                for (int ni = 0; ni < 4; ni++)
                    MMA16816(cr[mi][ni], afr[mi], bfr[ni]);
        }
    }

    float* gbd = gd_blank + (size_t)b * ND * 128;
    float* gld = gd_lab   + (size_t)b * ND * 128;
#pragma unroll
    for (int mi = 0; mi < 2; mi++) {
#pragma unroll
        for (int h = 0; h < 2; h++) {
            int t = t0 + wm * 32 + mi * 16 + h * 8 + (lane >> 2);
            const float* Er = E + (size_t)(b * Tn + t) * Vn;
            float e0 = Er[0];
#pragma unroll
            for (int ni = 0; ni < 4; ni++) {
#pragma unroll
                for (int j = 0; j < 2; j++) {
                    int u = wn * 32 + ni * 8 + (lane & 3) * 2 + j;
                    float ln = __logf(cr[mi][ni][h * 2 + j]);
                    gbd[(t + u) * 128 + u] = e0 + p0s[u] - ln;
                    if (u < Um1)
                        gld[(t + u) * 128 + u] = Er[lbs[u]] + pls[u] - ln;
                }
            }
        }
    }
}

// ---------------- kernel 3: DP, 2 batches interleaved per warp ---------------
// 16 blocks x 32 threads. Each warp advances TWO independent batch chains so
// their shfl/LDS/MUFU stalls overlap. cp.async ring per batch, 16 slots.
#define RING 16

__device__ __forceinline__ float lse_cell(int d, int u, float a_u, float a_um1,
                                          float bvv, float lvv) {
    const float NEG = -1e30f;
    int t = d - u;
    if (t < 0 || t > Tn - 1) return NEG;
    float v = (t >= 1) ? (a_u + bvv) : NEG;
    float h = (u >= 1) ? (a_um1 + lvv) : NEG;
    float m = fmaxf(v, h);
    float z = fminf(v, h) - m;
    return m + __logf(1.0f + __expf(z));
}

__global__ __launch_bounds__(32) void dp_kernel(const int* __restrict__ ilen,
                                                const int* __restrict__ llen,
                                                float* __restrict__ out) {
    __shared__ __align__(16) float ring[2][RING * 256];   // 32 KB
    const float NEG = -1e30f;
    int lane = threadIdx.x;          // 32
    int b0 = blockIdx.x * 2;
    int b1 = b0 + 1;
    int u0 = lane * 4;

    const float* gb0 = gd_blank + (size_t)b0 * ND * 128;
    const float* gl0 = gd_lab   + (size_t)b0 * ND * 128;
    const float* gb1 = gd_blank + (size_t)b1 * ND * 128;
    const float* gl1 = gd_lab   + (size_t)b1 * ND * 128;

    int Tl0 = ilen[b0], Ul0 = llen[b0], dfin0 = Tl0 - 1 + Ul0;
    int Tl1 = ilen[b1], Ul1 = llen[b1], dfin1 = Tl1 - 1 + Ul1;
    bool own0 = (u0 <= Ul0) && (Ul0 < u0 + 4);
    bool own1 = (u0 <= Ul1) && (Ul1 < u0 + 4);
    float bfin0 = gb0[(size_t)dfin0 * 128 + Ul0];
    float bfin1 = gb1[(size_t)dfin1 * 128 + Ul1];

    uint32_t r0b = smem_u32(&ring[0][0]);
    uint32_t r1b = smem_u32(&ring[1][0]);
    uint32_t my_off = (uint32_t)(lane * 16);

    // issue operand row r for both batches; ONE commit group per call
#define DP_ISSUE2(rr_) do {                                                  \
        int _r = (rr_); int _rc = _r <= 381 ? _r : 381;                      \
        uint32_t _so = (uint32_t)((_r & (RING - 1)) * 1024) + my_off;        \
        size_t _go = (size_t)_rc * 128 + u0;                                 \
        CP16(r0b + _so,       gb0 + _go);                                    \
        CP16(r0b + _so + 512, gl0 + _go);                                    \
        CP16(r1b + _so,       gb1 + _go);                                    \
        CP16(r1b + _so + 512, gl1 + _go);                                    \
        CP_COMMIT();                                                         \
    } while (0)

#pragma unroll
    for (int r = 0; r < 15; r++) DP_ISSUE2(r);
    asm volatile("cp.async.wait_group 13;" ::: "memory");   // rows 0,1 resident

    float4 bvc0 = *(float4*)&ring[0][0 * 256 + lane * 4];
    float4 lvc0 = *(float4*)&ring[0][0 * 256 + 128 + lane * 4];
    float4 bvn0 = *(float4*)&ring[0][1 * 256 + lane * 4];
    float4 lvn0 = *(float4*)&ring[0][1 * 256 + 128 + lane * 4];
    float4 bvc1 = *(float4*)&ring[1][0 * 256 + lane * 4];
    float4 lvc1 = *(float4*)&ring[1][0 * 256 + 128 + lane * 4];
    float4 bvn1 = *(float4*)&ring[1][1 * 256 + lane * 4];
    float4 lvn1 = *(float4*)&ring[1][1 * 256 + 128 + lane * 4];

    float a00 = (u0 == 0) ? 0.0f : NEG, a01 = NEG, a02 = NEG, a03 = NEG;
    float a10 = (u0 == 0) ? 0.0f : NEG, a11 = NEG, a12 = NEG, a13 = NEG;

    for (int r = 0; r < 382; r++) {
        int d = r + 1;

        float am10 = __shfl_up_sync(0xffffffffu, a03, 1);
        float lm10 = __shfl_up_sync(0xffffffffu, lvc0.w, 1);
        float am11 = __shfl_up_sync(0xffffffffu, a13, 1);
        float lm11 = __shfl_up_sync(0xffffffffu, lvc1.w, 1);

        float n00 = lse_cell(d, u0 + 0, a00, am10, bvc0.x, lm10);
        float n10 = lse_cell(d, u0 + 0, a10, am11, bvc1.x, lm11);
        float n01 = lse_cell(d, u0 + 1, a01, a00,  bvc0.y, lvc0.x);
        float n11 = lse_cell(d, u0 + 1, a11, a10,  bvc1.y, lvc1.x);
        float n02 = lse_cell(d, u0 + 2, a02, a01,  bvc0.z, lvc0.y);
        float n12 = lse_cell(d, u0 + 2, a12, a11,  bvc1.z, lvc1.y);
        float n03 = lse_cell(d, u0 + 3, a03, a02,  bvc0.w, lvc0.z);
        float n13 = lse_cell(d, u0 + 3, a13, a12,  bvc1.w, lvc1.z);
        a00 = n00; a01 = n01; a02 = n02; a03 = n03;
        a10 = n10; a11 = n11; a12 = n12; a13 = n13;

        if (d == dfin0 && own0) {
            int j = Ul0 & 3;
            float av = (j == 0) ? n00 : (j == 1) ? n01 : (j == 2) ? n02 : n03;
            out[b0] = -(av + bfin0);
        }
        if (d == dfin1 && own1) {
            int j = Ul1 & 3;
            float av = (j == 0) ? n10 : (j == 1) ? n11 : (j == 2) ? n12 : n13;
            out[b1] = -(av + bfin1);
        }

        DP_ISSUE2(r + 15);
        asm volatile("cp.async.wait_group 13;" ::: "memory");
        int s2 = (r + 2) & (RING - 1);
        float4 f0 = *(float4*)&ring[0][s2 * 256 + lane * 4];
        float4 g0 = *(float4*)&ring[0][s2 * 256 + 128 + lane * 4];
        float4 f1 = *(float4*)&ring[1][s2 * 256 + lane * 4];
        float4 g1 = *(float4*)&ring[1][s2 * 256 + 128 + lane * 4];
        bvc0 = bvn0; lvc0 = lvn0; bvn0 = f0; lvn0 = g0;
        bvc1 = bvn1; lvc1 = lvn1; bvn1 = f1; lvn1 = g1;
    }
#undef DP_ISSUE2
}

// ---------------- launcher ---------------------------------------------------
extern "C" void kernel_launch(void* const* d_in, const int* in_sizes, int n_in,
                              void* d_out, int out_size) {
    const float* e      = (const float*)d_in[0];
    const float* p      = (const float*)d_in[1];
    const int*   labels = (const int*)  d_in[2];
    const int*   ilen   = (const int*)  d_in[3];
    const int*   llen   = (const int*)  d_in[4];
    float* out = (float*)d_out;

    cudaFuncSetAttribute(gemm_kernel,
                         cudaFuncAttributeMaxDynamicSharedMemorySize, SMEM_TOT);

    expcvt_kernel<<<24576, 256>>>(e, p);
    gemm_kernel<<<dim3(4, Bn), 256, SMEM_TOT>>>(e, p, labels);
    dp_kernel<<<Bn / 2, 32>>>(ilen, llen, out);
}